// round 2
// baseline (speedup 1.0000x reference)
#include <cuda_runtime.h>
#include <math.h>

// Problem constants (fixed by setup_inputs)
#define B_  2
#define T_  8
#define M_  900
#define H_  27
#define W_  27
#define D_  1024
#define PATCH_ 14

#define NBLK (B_ * M_)                    // 1800 blocks, one per (b, m)
#define NPAIR_DENOM (B_ * (T_ - 1) * M_)  // 12600, mean denominator

__device__ float g_partials[NBLK];

__global__ __launch_bounds__(256, 8)
void gather_l1_kernel(const float* __restrict__ features,
                      const float* __restrict__ tracks,
                      const int* __restrict__ vis)   // bool stored as int32
{
    const int bm  = blockIdx.x;          // 0..1799
    const int b   = bm / M_;
    const int m   = bm - b * M_;
    const int tid = threadIdx.x;         // 256 threads = 1024 floats / 4

    __shared__ int s_nn[T_];
    __shared__ int s_vis[T_];

    if (tid < T_) {
        const int t = tid;
        // tracks layout: [B, T, M, 2] (x, y) in pixel space
        const float* tr = tracks + (((size_t)(b * T_ + t) * M_ + m) * 2);
        float x = tr[0];
        float y = tr[1];
        // nearest patch center c_j = 14j+7  ->  j = clamp(floor(x/14), 0, 26)
        int j = (int)floorf(x * (1.0f / PATCH_));
        int i = (int)floorf(y * (1.0f / PATCH_));
        j = min(W_ - 1, max(0, j));
        i = min(H_ - 1, max(0, i));
        s_nn[t]  = i * W_ + j;
        s_vis[t] = vis[(size_t)(b * T_ + t) * M_ + m];
    }
    __syncthreads();

    // Gather 8 rows; each thread owns one float4 lane -> 8 independent LDG.128
    float4 pf[T_];
#pragma unroll
    for (int t = 0; t < T_; t++) {
        const float4* row = (const float4*)(features
            + ((size_t)(b * T_ + t) * (H_ * W_) + s_nn[t]) * D_);
        pf[t] = row[tid];
    }

    float acc = 0.0f;
#pragma unroll
    for (int t = 0; t < T_ - 1; t++) {
        // L1 over this thread's 4 dims for pair (t, t+1) and pair (0, t+1)
        float l1c = fabsf(pf[t].x - pf[t + 1].x)
                  + fabsf(pf[t].y - pf[t + 1].y)
                  + fabsf(pf[t].z - pf[t + 1].z)
                  + fabsf(pf[t].w - pf[t + 1].w);
        float l1r = fabsf(pf[0].x - pf[t + 1].x)
                  + fabsf(pf[0].y - pf[t + 1].y)
                  + fabsf(pf[0].z - pf[t + 1].z)
                  + fabsf(pf[0].w - pf[t + 1].w);
        if (s_vis[t] && s_vis[t + 1]) acc += l1c;
        if (s_vis[0] && s_vis[t + 1]) acc += l1r;
    }

    // Block reduction: warp shuffle, then 8 warp sums via shared
#pragma unroll
    for (int o = 16; o > 0; o >>= 1)
        acc += __shfl_down_sync(0xffffffffu, acc, o);

    __shared__ float s_warp[8];
    const int lane = tid & 31;
    const int wid  = tid >> 5;
    if (lane == 0) s_warp[wid] = acc;
    __syncthreads();
    if (tid == 0) {
        float s = 0.0f;
#pragma unroll
        for (int w = 0; w < 8; w++) s += s_warp[w];
        g_partials[bm] = s;
    }
}

__global__ void finalize_kernel(float* __restrict__ out)
{
    const int tid = threadIdx.x;  // 256
    double acc = 0.0;
    for (int i = tid; i < NBLK; i += 256)
        acc += (double)g_partials[i];

#pragma unroll
    for (int o = 16; o > 0; o >>= 1)
        acc += __shfl_down_sync(0xffffffffu, acc, o);

    __shared__ double s_warp[8];
    const int lane = tid & 31;
    const int wid  = tid >> 5;
    if (lane == 0) s_warp[wid] = acc;
    __syncthreads();
    if (tid == 0) {
        double s = 0.0;
#pragma unroll
        for (int w = 0; w < 8; w++) s += s_warp[w];
        out[0] = (float)(0.01 * s / (double)NPAIR_DENOM);
    }
}

extern "C" void kernel_launch(void* const* d_in, const int* in_sizes, int n_in,
                              void* d_out, int out_size)
{
    const float* features = (const float*)d_in[0];  // [B*T, H*W, D] f32
    const float* tracks   = (const float*)d_in[1];  // [B, T, M, 2]  f32
    const int*   vis      = (const int*)d_in[2];    // [B, T, M]     bool->int32
    float*       out      = (float*)d_out;

    gather_l1_kernel<<<NBLK, 256>>>(features, tracks, vis);
    finalize_kernel<<<1, 256>>>(out);
}